// round 15
// baseline (speedup 1.0000x reference)
#include <cuda_runtime.h>
#include <cuda_fp16.h>
#include <math.h>
#include <stdint.h>

#define DM    1024
#define FFN_  4096
#define NE    8
#define TMAX  8192

// ---------------- device scratch (static per-expert capacity layout) ----------------
__device__ int    g_counts[NE];
__device__ int    g_tok[NE][TMAX];
__device__ float  g_gate[NE][TMAX];
__device__ __half g_Xgh[(size_t)NE * TMAX * DM];
__device__ __half g_Hh[(size_t)NE * TMAX * FFN_];
__device__ __half g_w1h[(size_t)NE * DM * FFN_];
__device__ __half g_w2h[(size_t)NE * FFN_ * DM];

// ---------------- helpers ----------------
__device__ __forceinline__ uint32_t smem_u32(const void* p) {
    uint32_t a;
    asm("{ .reg .u64 t; cvta.to.shared.u64 t, %1; cvt.u32.u64 %0, t; }" : "=r"(a) : "l"(p));
    return a;
}
__device__ __forceinline__ float gelu_exact(float v) {
    return 0.5f * v * (1.f + erff(v * 0.7071067811865476f));
}

#define CP_ASYNC16(dst, src) \
    asm volatile("cp.async.cg.shared.global [%0], [%1], 16;" :: "r"(dst), "l"(src) : "memory")
#define CP_COMMIT()  asm volatile("cp.async.commit_group;" ::: "memory")
#define CP_WAIT2()   asm volatile("cp.async.wait_group 2;" ::: "memory")

#define LDMATRIX_X4(r0,r1,r2,r3, addr) \
    asm volatile("ldmatrix.sync.aligned.m8n8.x4.shared.b16 {%0,%1,%2,%3}, [%4];" \
        : "=r"(r0), "=r"(r1), "=r"(r2), "=r"(r3) : "r"(addr))
#define LDMATRIX_X4_T(r0,r1,r2,r3, addr) \
    asm volatile("ldmatrix.sync.aligned.m8n8.x4.trans.shared.b16 {%0,%1,%2,%3}, [%4];" \
        : "=r"(r0), "=r"(r1), "=r"(r2), "=r"(r3) : "r"(addr))

#define MMA_F16(c, a, b0, b1) \
    asm volatile("mma.sync.aligned.m16n8k16.row.col.f32.f16.f16.f32 " \
        "{%0,%1,%2,%3}, {%4,%5,%6,%7}, {%8,%9}, {%0,%1,%2,%3};" \
        : "+f"((c)[0]), "+f"((c)[1]), "+f"((c)[2]), "+f"((c)[3]) \
        : "r"((a)[0]), "r"((a)[1]), "r"((a)[2]), "r"((a)[3]), "r"(b0), "r"(b1))

// ---------------- routing (fused with gather) ----------------
__global__ void init_kernel() { if (threadIdx.x < NE) g_counts[threadIdx.x] = 0; }

__global__ void route_gather_kernel(const float* __restrict__ x,
                                    const float* __restrict__ gw,
                                    const float* __restrict__ gb, int T) {
    int warp = (blockIdx.x * blockDim.x + threadIdx.x) >> 5;
    int lane = threadIdx.x & 31;
    if (warp >= T) return;
    const float* xr = x + (size_t)warp * DM;
    float acc[NE];
    #pragma unroll
    for (int e = 0; e < NE; e++) acc[e] = 0.f;
    for (int d = lane; d < DM; d += 32) {
        float xv = xr[d];
        const float4* g4 = (const float4*)(gw + (size_t)d * NE);
        float4 a = g4[0], b = g4[1];
        acc[0] += xv*a.x; acc[1] += xv*a.y; acc[2] += xv*a.z; acc[3] += xv*a.w;
        acc[4] += xv*b.x; acc[5] += xv*b.y; acc[6] += xv*b.z; acc[7] += xv*b.w;
    }
    #pragma unroll
    for (int e = 0; e < NE; e++)
        #pragma unroll
        for (int o = 16; o > 0; o >>= 1) acc[e] += __shfl_xor_sync(0xFFFFFFFFu, acc[e], o);

    int i1 = 0, i2 = 0, s1 = 0, s2 = 0;
    if (lane == 0) {
        float v[NE];
        #pragma unroll
        for (int e = 0; e < NE; e++) v[e] = acc[e] + gb[e];
        i1 = 0;
        #pragma unroll
        for (int e = 1; e < NE; e++) if (v[e] > v[i1]) i1 = e;
        i2 = (i1 == 0) ? 1 : 0;
        #pragma unroll
        for (int e = 0; e < NE; e++) if (e != i1 && v[e] > v[i2]) i2 = e;
        float e2 = expf(v[i2] - v[i1]);
        float s = 1.f + e2;
        s1 = atomicAdd(&g_counts[i1], 1);
        g_tok[i1][s1] = warp; g_gate[i1][s1] = 1.f / s;
        s2 = atomicAdd(&g_counts[i2], 1);
        g_tok[i2][s2] = warp; g_gate[i2][s2] = e2 / s;
    }
    i1 = __shfl_sync(0xFFFFFFFFu, i1, 0);
    i2 = __shfl_sync(0xFFFFFFFFu, i2, 0);
    s1 = __shfl_sync(0xFFFFFFFFu, s1, 0);
    s2 = __shfl_sync(0xFFFFFFFFu, s2, 0);

    const float4* src = (const float4*)xr;
    uint2* d1 = (uint2*)(g_Xgh + ((size_t)i1 * TMAX + s1) * DM);
    uint2* d2 = (uint2*)(g_Xgh + ((size_t)i2 * TMAX + s2) * DM);
    #pragma unroll
    for (int j = 0; j < 8; j++) {
        int idx = lane + j * 32;
        float4 v = src[idx];
        __half2 h0 = __floats2half2_rn(v.x, v.y);
        __half2 h1 = __floats2half2_rn(v.z, v.w);
        uint2 o;
        o.x = *reinterpret_cast<uint32_t*>(&h0);
        o.y = *reinterpret_cast<uint32_t*>(&h1);
        d1[idx] = o;
        d2[idx] = o;
    }
}

// fp32 -> fp16 weight conversion
__global__ void conv_half_kernel(const float4* __restrict__ src, uint4* __restrict__ dst, int n8) {
    int i = blockIdx.x * blockDim.x + threadIdx.x;
    if (i >= n8) return;
    float4 v0 = src[i * 2], v1 = src[i * 2 + 1];
    __half2 h0 = __floats2half2_rn(v0.x, v0.y);
    __half2 h1 = __floats2half2_rn(v0.z, v0.w);
    __half2 h2 = __floats2half2_rn(v1.x, v1.y);
    __half2 h3 = __floats2half2_rn(v1.z, v1.w);
    uint4 o;
    o.x = *reinterpret_cast<uint32_t*>(&h0);
    o.y = *reinterpret_cast<uint32_t*>(&h1);
    o.z = *reinterpret_cast<uint32_t*>(&h2);
    o.w = *reinterpret_cast<uint32_t*>(&h3);
    dst[i] = o;
}

// ---------------- fp16 mma grouped GEMM (per-expert launch) ----------------
#define ASTRH 40
#define BSTRH 136
#define ABUFB (128 * ASTRH * 2)
#define BBUFB (32 * BSTRH * 2)
#define BUFB  (ABUFB + BBUFB)
#define NSTAGE 4
#define SMEM_DYN (NSTAGE * BUFB)

template<int KDIM, int NDIM, bool GELU_OUT>
__global__ void __launch_bounds__(256, 2)
gemm_mma(const __half* __restrict__ Bmat, const float* __restrict__ bias,
         float* __restrict__ outp, int e) {
    const int count = g_counts[e];
    const int m0 = blockIdx.x * 128;
    if (m0 >= count) return;
    const size_t base = (size_t)e * TMAX;
    const int n0 = blockIdx.y * 128;

    extern __shared__ char smraw[];
    const uint32_t su = smem_u32(smraw);

    const int tid  = threadIdx.x;
    const int wid  = tid >> 5;
    const int lane = tid & 31;
    const int g    = lane >> 2;
    const int tg   = lane & 3;
    const int wr   = wid & 1;
    const int wc   = wid >> 1;

    const __half* Asrc = (GELU_OUT ? g_Xgh : g_Hh) + (base + m0) * KDIM;
    const __half* Bsrc = Bmat + (size_t)e * KDIM * NDIM + n0;

    const int am = tid >> 1;
    const int ac = (tid & 1) * 2;
    const int bk = tid >> 3;
    const int bc = (tid & 7) * 2;

    const int lane_r  = (lane & 7) + ((lane >> 3) & 1) * 8;
    const int lane_k8 = (lane >> 4) * 16;

    float c[4][4][4];
    #pragma unroll
    for (int i = 0; i < 4; i++)
        #pragma unroll
        for (int j = 0; j < 4; j++)
            #pragma unroll
            for (int k = 0; k < 4; k++) c[i][j][k] = 0.f;

    const int KC = KDIM / 32;

    #define LOAD_TILES(kc_, buf_) do { \
        uint32_t sa = su + (buf_) * BUFB; \
        uint32_t sb = sa + ABUFB; \
        const __half* asp = Asrc + (size_t)am * KDIM + (kc_) * 32; \
        _Pragma("unroll") \
        for (int j = 0; j < 2; j++) \
            CP_ASYNC16(sa + (uint32_t)(am * 80 + (ac + j) * 16), asp + (ac + j) * 8); \
        const __half* bsp = Bsrc + (size_t)((kc_) * 32 + bk) * NDIM; \
        _Pragma("unroll") \
        for (int j = 0; j < 2; j++) \
            CP_ASYNC16(sb + (uint32_t)(bk * 272 + (bc + j) * 16), bsp + (bc + j) * 8); \
    } while (0)

    LOAD_TILES(0, 0); CP_COMMIT();
    LOAD_TILES(1, 1); CP_COMMIT();
    LOAD_TILES(2, 2); CP_COMMIT();

    for (int kc = 0; kc < KC; kc++) {
        CP_WAIT2();
        __syncthreads();
        if (kc + 3 < KC) LOAD_TILES(kc + 3, (kc + 3) & 3);
        CP_COMMIT();

        const uint32_t sa = su + (kc & 3) * BUFB;
        const uint32_t sb = sa + ABUFB;
        const uint32_t a_base = sa + (uint32_t)((wr * 64 + lane_r) * 80) + lane_k8;
        const uint32_t b_base = sb + (uint32_t)(lane_r * 272 + wc * 64) + lane_k8;

        #pragma unroll
        for (int ks = 0; ks < 2; ks++) {
            uint32_t a[4][4];
            #pragma unroll
            for (int mf = 0; mf < 4; mf++)
                LDMATRIX_X4(a[mf][0], a[mf][1], a[mf][2], a[mf][3],
                            a_base + mf * 1280 + ks * 32);
            uint32_t b[4][2];
            #pragma unroll
            for (int np = 0; np < 2; np++) {
                uint32_t r0, r1, r2, r3;
                LDMATRIX_X4_T(r0, r1, r2, r3, b_base + ks * 4352 + np * 32);
                b[np * 2 + 0][0] = r0; b[np * 2 + 0][1] = r1;
                b[np * 2 + 1][0] = r2; b[np * 2 + 1][1] = r3;
            }
            #pragma unroll
            for (int mf = 0; mf < 4; mf++)
                #pragma unroll
                for (int nf = 0; nf < 4; nf++)
                    MMA_F16(c[mf][nf], a[mf], b[nf][0], b[nf][1]);
        }
    }

    // -------- epilogue --------
    #pragma unroll
    for (int mf = 0; mf < 4; mf++) {
        #pragma unroll
        for (int half_ = 0; half_ < 2; half_++) {
            int rl = wr * 64 + mf * 16 + g + half_ * 8;
            int m = m0 + rl;
            if (m >= count) continue;
            if (GELU_OUT) {
                __half* hrow = g_Hh + (base + m) * FFN_;
                #pragma unroll
                for (int nf = 0; nf < 4; nf++) {
                    int col = n0 + wc * 32 + nf * 8 + 2 * tg;
                    float2 bb = *(const float2*)(bias + (size_t)e * NDIM + col);
                    __half2 hv = __floats2half2_rn(
                        gelu_exact(c[mf][nf][half_ * 2 + 0] + bb.x),
                        gelu_exact(c[mf][nf][half_ * 2 + 1] + bb.y));
                    *reinterpret_cast<__half2*>(hrow + col) = hv;
                }
            } else {
                int tok = g_tok[e][m];
                float gt = g_gate[e][m];
                float* orow = outp + (size_t)tok * DM;
                #pragma unroll
                for (int nf = 0; nf < 4; nf++) {
                    int col = n0 + wc * 32 + nf * 8 + 2 * tg;
                    float2 bb = *(const float2*)(bias + (size_t)e * NDIM + col);
                    atomicAdd(orow + col + 0, gt * (c[mf][nf][half_ * 2 + 0] + bb.x));
                    atomicAdd(orow + col + 1, gt * (c[mf][nf][half_ * 2 + 1] + bb.y));
                }
            }
        }
    }
}

// ---------------- launch ----------------
extern "C" void kernel_launch(void* const* d_in, const int* in_sizes, int n_in,
                              void* d_out, int out_size) {
    const float* x  = (const float*)d_in[0];
    const float* gw = (const float*)d_in[1];
    const float* gb = (const float*)d_in[2];
    const float* w1 = (const float*)d_in[3];
    const float* b1 = (const float*)d_in[4];
    const float* w2 = (const float*)d_in[5];
    const float* b2 = (const float*)d_in[6];
    float* out = (float*)d_out;
    const int T = in_sizes[0] / DM;
    const int MB = T / 128;   // CTA rows per expert (capacity grid)

    __half* w1h; cudaGetSymbolAddress((void**)&w1h, g_w1h);
    __half* w2h; cudaGetSymbolAddress((void**)&w2h, g_w2h);

    static cudaStream_t s1 = nullptr;
    static cudaEvent_t evRoot = nullptr, evW1 = nullptr, evFin = nullptr;
    static cudaEvent_t ev1[NE];
    static int once = 0;
    if (!once) {
        cudaStreamCreateWithFlags(&s1, cudaStreamNonBlocking);
        cudaEventCreateWithFlags(&evRoot, cudaEventDisableTiming);
        cudaEventCreateWithFlags(&evW1, cudaEventDisableTiming);
        cudaEventCreateWithFlags(&evFin, cudaEventDisableTiming);
        for (int e = 0; e < NE; e++)
            cudaEventCreateWithFlags(&ev1[e], cudaEventDisableTiming);
        cudaFuncSetAttribute(gemm_mma<DM, FFN_, true>,
                             cudaFuncAttributeMaxDynamicSharedMemorySize, SMEM_DYN);
        cudaFuncSetAttribute(gemm_mma<FFN_, DM, false>,
                             cudaFuncAttributeMaxDynamicSharedMemorySize, SMEM_DYN);
        once = 1;
    }

    const int n8 = NE * DM * FFN_ / 8;

    // fork side stream: conv w1, conv w2, memset(out)
    cudaEventRecord(evRoot, 0);
    cudaStreamWaitEvent(s1, evRoot, 0);
    conv_half_kernel<<<(n8 + 255) / 256, 256, 0, s1>>>((const float4*)w1, (uint4*)w1h, n8);
    cudaEventRecord(evW1, s1);
    conv_half_kernel<<<(n8 + 255) / 256, 256, 0, s1>>>((const float4*)w2, (uint4*)w2h, n8);
    cudaMemsetAsync(d_out, 0, (size_t)out_size * sizeof(float), s1);

    // main stream: routing (fused gather)
    init_kernel<<<1, 32>>>();
    route_gather_kernel<<<(T + 7) / 8, 256>>>(x, gw, gb, T);
    cudaStreamWaitEvent(0, evW1, 0);

    // per-expert GEMM1 chain on stream 0, GEMM2 pipelined on s1
    for (int e = 0; e < NE; e++) {
        gemm_mma<DM, FFN_, true><<<dim3(MB, FFN_ / 128), 256, SMEM_DYN, 0>>>(w1h, b1, nullptr, e);
        cudaEventRecord(ev1[e], 0);
    }
    for (int e = 0; e < NE; e++) {
        cudaStreamWaitEvent(s1, ev1[e], 0);
        gemm_mma<FFN_, DM, false><<<dim3(MB, DM / 128), 256, SMEM_DYN, s1>>>(w2h, b2, out, e);
    }
    cudaEventRecord(evFin, s1);
    cudaStreamWaitEvent(0, evFin, 0);
}

// round 16
// speedup vs baseline: 1.2139x; 1.2139x over previous
#include <cuda_runtime.h>
#include <cuda_fp16.h>
#include <math.h>
#include <stdint.h>

#define DM    1024
#define FFN_  4096
#define NE    8
#define TMAX  8192

// ---------------- device scratch (static per-expert capacity layout) ----------------
__device__ int    g_counts[NE];
__device__ int    g_tok[NE][TMAX];
__device__ float  g_gate[NE][TMAX];
__device__ __half g_Xgh[(size_t)NE * TMAX * DM];
__device__ __half g_Hh[(size_t)NE * TMAX * FFN_];
__device__ __half g_w1h[(size_t)NE * DM * FFN_];
__device__ __half g_w2h[(size_t)NE * FFN_ * DM];

// ---------------- helpers ----------------
__device__ __forceinline__ uint32_t smem_u32(const void* p) {
    uint32_t a;
    asm("{ .reg .u64 t; cvta.to.shared.u64 t, %1; cvt.u32.u64 %0, t; }" : "=r"(a) : "l"(p));
    return a;
}
__device__ __forceinline__ float gelu_exact(float v) {
    return 0.5f * v * (1.f + erff(v * 0.7071067811865476f));
}

#define CP_ASYNC16(dst, src) \
    asm volatile("cp.async.cg.shared.global [%0], [%1], 16;" :: "r"(dst), "l"(src) : "memory")
#define CP_COMMIT()  asm volatile("cp.async.commit_group;" ::: "memory")
#define CP_WAIT2()   asm volatile("cp.async.wait_group 2;" ::: "memory")

#define LDMATRIX_X4(r0,r1,r2,r3, addr) \
    asm volatile("ldmatrix.sync.aligned.m8n8.x4.shared.b16 {%0,%1,%2,%3}, [%4];" \
        : "=r"(r0), "=r"(r1), "=r"(r2), "=r"(r3) : "r"(addr))
#define LDMATRIX_X4_T(r0,r1,r2,r3, addr) \
    asm volatile("ldmatrix.sync.aligned.m8n8.x4.trans.shared.b16 {%0,%1,%2,%3}, [%4];" \
        : "=r"(r0), "=r"(r1), "=r"(r2), "=r"(r3) : "r"(addr))

#define MMA_F16(c, a, b0, b1) \
    asm volatile("mma.sync.aligned.m16n8k16.row.col.f32.f16.f16.f32 " \
        "{%0,%1,%2,%3}, {%4,%5,%6,%7}, {%8,%9}, {%0,%1,%2,%3};" \
        : "+f"((c)[0]), "+f"((c)[1]), "+f"((c)[2]), "+f"((c)[3]) \
        : "r"((a)[0]), "r"((a)[1]), "r"((a)[2]), "r"((a)[3]), "r"(b0), "r"(b1))

// ---------------- routing (fused gather, register-cached x) ----------------
__global__ void route_gather_kernel(const float* __restrict__ x,
                                    const float* __restrict__ gw,
                                    const float* __restrict__ gb, int T) {
    int warp = (blockIdx.x * blockDim.x + threadIdx.x) >> 5;
    int lane = threadIdx.x & 31;
    if (warp >= T) return;
    const float4* x4 = (const float4*)(x + (size_t)warp * DM);

    // load token row once: 8 x float4 per lane (covers 1024 floats / warp)
    float4 xv[8];
    #pragma unroll
    for (int j = 0; j < 8; j++) xv[j] = x4[lane + j * 32];

    float acc[NE];
    #pragma unroll
    for (int e = 0; e < NE; e++) acc[e] = 0.f;

    #pragma unroll
    for (int j = 0; j < 8; j++) {
        int d0 = (lane + j * 32) * 4;
        float xs[4] = {xv[j].x, xv[j].y, xv[j].z, xv[j].w};
        #pragma unroll
        for (int cc = 0; cc < 4; cc++) {
            const float4* g4 = (const float4*)(gw + (size_t)(d0 + cc) * NE);
            float4 a = g4[0], b = g4[1];
            float xf = xs[cc];
            acc[0] += xf*a.x; acc[1] += xf*a.y; acc[2] += xf*a.z; acc[3] += xf*a.w;
            acc[4] += xf*b.x; acc[5] += xf*b.y; acc[6] += xf*b.z; acc[7] += xf*b.w;
        }
    }
    #pragma unroll
    for (int e = 0; e < NE; e++)
        #pragma unroll
        for (int o = 16; o > 0; o >>= 1) acc[e] += __shfl_xor_sync(0xFFFFFFFFu, acc[e], o);

    int i1 = 0, i2 = 0, s1 = 0, s2 = 0;
    if (lane == 0) {
        float v[NE];
        #pragma unroll
        for (int e = 0; e < NE; e++) v[e] = acc[e] + gb[e];
        i1 = 0;
        #pragma unroll
        for (int e = 1; e < NE; e++) if (v[e] > v[i1]) i1 = e;
        i2 = (i1 == 0) ? 1 : 0;
        #pragma unroll
        for (int e = 0; e < NE; e++) if (e != i1 && v[e] > v[i2]) i2 = e;
        float e2 = expf(v[i2] - v[i1]);
        float s = 1.f + e2;
        s1 = atomicAdd(&g_counts[i1], 1);
        g_tok[i1][s1] = warp; g_gate[i1][s1] = 1.f / s;
        s2 = atomicAdd(&g_counts[i2], 1);
        g_tok[i2][s2] = warp; g_gate[i2][s2] = e2 / s;
    }
    i1 = __shfl_sync(0xFFFFFFFFu, i1, 0);
    i2 = __shfl_sync(0xFFFFFFFFu, i2, 0);
    s1 = __shfl_sync(0xFFFFFFFFu, s1, 0);
    s2 = __shfl_sync(0xFFFFFFFFu, s2, 0);

    // fused gather from registers (no re-read of x)
    uint2* d1 = (uint2*)(g_Xgh + ((size_t)i1 * TMAX + s1) * DM);
    uint2* d2 = (uint2*)(g_Xgh + ((size_t)i2 * TMAX + s2) * DM);
    #pragma unroll
    for (int j = 0; j < 8; j++) {
        int idx = lane + j * 32;
        __half2 h0 = __floats2half2_rn(xv[j].x, xv[j].y);
        __half2 h1 = __floats2half2_rn(xv[j].z, xv[j].w);
        uint2 o;
        o.x = *reinterpret_cast<uint32_t*>(&h0);
        o.y = *reinterpret_cast<uint32_t*>(&h1);
        d1[idx] = o;
        d2[idx] = o;
    }
}

// fp32 -> fp16 weight conversion
__global__ void conv_half_kernel(const float4* __restrict__ src, uint4* __restrict__ dst, int n8) {
    int i = blockIdx.x * blockDim.x + threadIdx.x;
    if (i >= n8) return;
    float4 v0 = src[i * 2], v1 = src[i * 2 + 1];
    __half2 h0 = __floats2half2_rn(v0.x, v0.y);
    __half2 h1 = __floats2half2_rn(v0.z, v0.w);
    __half2 h2 = __floats2half2_rn(v1.x, v1.y);
    __half2 h3 = __floats2half2_rn(v1.z, v1.w);
    uint4 o;
    o.x = *reinterpret_cast<uint32_t*>(&h0);
    o.y = *reinterpret_cast<uint32_t*>(&h1);
    o.z = *reinterpret_cast<uint32_t*>(&h2);
    o.w = *reinterpret_cast<uint32_t*>(&h3);
    dst[i] = o;
}

// ---------------- fp16 mma grouped GEMM (R5 config, static bases) ----------------
#define ASTRH 40
#define BSTRH 136
#define ABUFB (128 * ASTRH * 2)
#define BBUFB (32 * BSTRH * 2)
#define BUFB  (ABUFB + BBUFB)
#define NSTAGE 4
#define SMEM_DYN (NSTAGE * BUFB)

template<int KDIM, int NDIM, bool GELU_OUT>
__global__ void __launch_bounds__(256, 2)
gemm_mma(const __half* __restrict__ Bmat, const float* __restrict__ bias,
         float* __restrict__ outp) {
    const int e = blockIdx.z;
    const int count = g_counts[e];
    const int m0 = blockIdx.x * 128;
    if (m0 >= count) return;
    const size_t base = (size_t)e * TMAX;
    const int n0 = blockIdx.y * 128;

    extern __shared__ char smraw[];
    const uint32_t su = smem_u32(smraw);

    const int tid  = threadIdx.x;
    const int wid  = tid >> 5;
    const int lane = tid & 31;
    const int g    = lane >> 2;
    const int tg   = lane & 3;
    const int wr   = wid & 1;
    const int wc   = wid >> 1;

    const __half* Asrc = (GELU_OUT ? g_Xgh : g_Hh) + (base + m0) * KDIM;
    const __half* Bsrc = Bmat + (size_t)e * KDIM * NDIM + n0;

    const int am = tid >> 1;
    const int ac = (tid & 1) * 2;
    const int bk = tid >> 3;
    const int bc = (tid & 7) * 2;

    const int lane_r  = (lane & 7) + ((lane >> 3) & 1) * 8;
    const int lane_k8 = (lane >> 4) * 16;

    float c[4][4][4];
    #pragma unroll
    for (int i = 0; i < 4; i++)
        #pragma unroll
        for (int j = 0; j < 4; j++)
            #pragma unroll
            for (int k = 0; k < 4; k++) c[i][j][k] = 0.f;

    const int KC = KDIM / 32;

    #define LOAD_TILES(kc_, buf_) do { \
        uint32_t sa = su + (buf_) * BUFB; \
        uint32_t sb = sa + ABUFB; \
        const __half* asp = Asrc + (size_t)am * KDIM + (kc_) * 32; \
        _Pragma("unroll") \
        for (int j = 0; j < 2; j++) \
            CP_ASYNC16(sa + (uint32_t)(am * 80 + (ac + j) * 16), asp + (ac + j) * 8); \
        const __half* bsp = Bsrc + (size_t)((kc_) * 32 + bk) * NDIM; \
        _Pragma("unroll") \
        for (int j = 0; j < 2; j++) \
            CP_ASYNC16(sb + (uint32_t)(bk * 272 + (bc + j) * 16), bsp + (bc + j) * 8); \
    } while (0)

    LOAD_TILES(0, 0); CP_COMMIT();
    LOAD_TILES(1, 1); CP_COMMIT();
    LOAD_TILES(2, 2); CP_COMMIT();

    for (int kc = 0; kc < KC; kc++) {
        CP_WAIT2();
        __syncthreads();
        if (kc + 3 < KC) LOAD_TILES(kc + 3, (kc + 3) & 3);
        CP_COMMIT();

        const uint32_t sa = su + (kc & 3) * BUFB;
        const uint32_t sb = sa + ABUFB;
        const uint32_t a_base = sa + (uint32_t)((wr * 64 + lane_r) * 80) + lane_k8;
        const uint32_t b_base = sb + (uint32_t)(lane_r * 272 + wc * 64) + lane_k8;

        #pragma unroll
        for (int ks = 0; ks < 2; ks++) {
            uint32_t a[4][4];
            #pragma unroll
            for (int mf = 0; mf < 4; mf++)
                LDMATRIX_X4(a[mf][0], a[mf][1], a[mf][2], a[mf][3],
                            a_base + mf * 1280 + ks * 32);
            uint32_t b[4][2];
            #pragma unroll
            for (int np = 0; np < 2; np++) {
                uint32_t r0, r1, r2, r3;
                LDMATRIX_X4_T(r0, r1, r2, r3, b_base + ks * 4352 + np * 32);
                b[np * 2 + 0][0] = r0; b[np * 2 + 0][1] = r1;
                b[np * 2 + 1][0] = r2; b[np * 2 + 1][1] = r3;
            }
            #pragma unroll
            for (int mf = 0; mf < 4; mf++)
                #pragma unroll
                for (int nf = 0; nf < 4; nf++)
                    MMA_F16(c[mf][nf], a[mf], b[nf][0], b[nf][1]);
        }
    }

    // -------- epilogue --------
    #pragma unroll
    for (int mf = 0; mf < 4; mf++) {
        #pragma unroll
        for (int half_ = 0; half_ < 2; half_++) {
            int rl = wr * 64 + mf * 16 + g + half_ * 8;
            int m = m0 + rl;
            if (m >= count) continue;
            if (GELU_OUT) {
                __half* hrow = g_Hh + (base + m) * FFN_;
                #pragma unroll
                for (int nf = 0; nf < 4; nf++) {
                    int col = n0 + wc * 32 + nf * 8 + 2 * tg;
                    float2 bb = *(const float2*)(bias + (size_t)e * NDIM + col);
                    __half2 hv = __floats2half2_rn(
                        gelu_exact(c[mf][nf][half_ * 2 + 0] + bb.x),
                        gelu_exact(c[mf][nf][half_ * 2 + 1] + bb.y));
                    *reinterpret_cast<__half2*>(hrow + col) = hv;
                }
            } else {
                int tok = g_tok[e][m];
                float gt = g_gate[e][m];
                float* orow = outp + (size_t)tok * DM;
                #pragma unroll
                for (int nf = 0; nf < 4; nf++) {
                    int col = n0 + wc * 32 + nf * 8 + 2 * tg;
                    float2 bb = *(const float2*)(bias + (size_t)e * NDIM + col);
                    atomicAdd(orow + col + 0, gt * (c[mf][nf][half_ * 2 + 0] + bb.x));
                    atomicAdd(orow + col + 1, gt * (c[mf][nf][half_ * 2 + 1] + bb.y));
                }
            }
        }
    }
}

// ---------------- launch ----------------
extern "C" void kernel_launch(void* const* d_in, const int* in_sizes, int n_in,
                              void* d_out, int out_size) {
    const float* x  = (const float*)d_in[0];
    const float* gw = (const float*)d_in[1];
    const float* gb = (const float*)d_in[2];
    const float* w1 = (const float*)d_in[3];
    const float* b1 = (const float*)d_in[4];
    const float* w2 = (const float*)d_in[5];
    const float* b2 = (const float*)d_in[6];
    float* out = (float*)d_out;
    const int T = in_sizes[0] / DM;

    __half* w1h; cudaGetSymbolAddress((void**)&w1h, g_w1h);
    __half* w2h; cudaGetSymbolAddress((void**)&w2h, g_w2h);
    int* cnts;   cudaGetSymbolAddress((void**)&cnts, g_counts);

    static cudaStream_t s1 = nullptr;
    static cudaEvent_t evRoot = nullptr, evW1 = nullptr, evW2 = nullptr;
    static int once = 0;
    if (!once) {
        cudaStreamCreateWithFlags(&s1, cudaStreamNonBlocking);
        cudaEventCreateWithFlags(&evRoot, cudaEventDisableTiming);
        cudaEventCreateWithFlags(&evW1, cudaEventDisableTiming);
        cudaEventCreateWithFlags(&evW2, cudaEventDisableTiming);
        cudaFuncSetAttribute(gemm_mma<DM, FFN_, true>,
                             cudaFuncAttributeMaxDynamicSharedMemorySize, SMEM_DYN);
        cudaFuncSetAttribute(gemm_mma<FFN_, DM, false>,
                             cudaFuncAttributeMaxDynamicSharedMemorySize, SMEM_DYN);
        once = 1;
    }

    const int n8 = NE * DM * FFN_ / 8;

    // fork side stream: conv w1, memset(out), conv w2
    cudaEventRecord(evRoot, 0);
    cudaStreamWaitEvent(s1, evRoot, 0);
    conv_half_kernel<<<(n8 + 255) / 256, 256, 0, s1>>>((const float4*)w1, (uint4*)w1h, n8);
    cudaEventRecord(evW1, s1);
    cudaMemsetAsync(d_out, 0, (size_t)out_size * sizeof(float), s1);
    conv_half_kernel<<<(n8 + 255) / 256, 256, 0, s1>>>((const float4*)w2, (uint4*)w2h, n8);
    cudaEventRecord(evW2, s1);

    // main stream: zero counts + fused routing/gather
    cudaMemsetAsync(cnts, 0, NE * sizeof(int), 0);
    route_gather_kernel<<<(T + 7) / 8, 256>>>(x, gw, gb, T);

    // join w1, run GEMM1 (conv w2 + memset overlap on s1)
    cudaStreamWaitEvent(0, evW1, 0);
    gemm_mma<DM, FFN_, true><<<dim3(T / 128, FFN_ / 128, NE), 256, SMEM_DYN>>>(w1h, b1, nullptr);

    // join w2 (+memset), run GEMM2
    cudaStreamWaitEvent(0, evW2, 0);
    gemm_mma<FFN_, DM, false><<<dim3(T / 128, DM / 128, NE), 256, SMEM_DYN>>>(w2h, b2, out);
}

// round 17
// speedup vs baseline: 1.2338x; 1.0164x over previous
#include <cuda_runtime.h>
#include <cuda_fp16.h>
#include <math.h>
#include <stdint.h>

#define DM    1024
#define FFN_  4096
#define NE    8
#define TMAX  8192

// ---------------- device scratch (static per-expert capacity layout) ----------------
__device__ int    g_counts[NE];
__device__ int    g_tok[NE][TMAX];
__device__ float  g_gate[NE][TMAX];
__device__ __half g_Xgh[(size_t)NE * TMAX * DM];
__device__ __half g_Hh[(size_t)NE * TMAX * FFN_];
__device__ __half g_w1h[(size_t)NE * DM * FFN_];
__device__ __half g_w2h[(size_t)NE * FFN_ * DM];

// ---------------- helpers ----------------
__device__ __forceinline__ uint32_t smem_u32(const void* p) {
    uint32_t a;
    asm("{ .reg .u64 t; cvta.to.shared.u64 t, %1; cvt.u32.u64 %0, t; }" : "=r"(a) : "l"(p));
    return a;
}
__device__ __forceinline__ float gelu_exact(float v) {
    return 0.5f * v * (1.f + erff(v * 0.7071067811865476f));
}

#define CP_ASYNC16(dst, src) \
    asm volatile("cp.async.cg.shared.global [%0], [%1], 16;" :: "r"(dst), "l"(src) : "memory")
#define CP_COMMIT()  asm volatile("cp.async.commit_group;" ::: "memory")
#define CP_WAIT2()   asm volatile("cp.async.wait_group 2;" ::: "memory")

#define LDMATRIX_X4(r0,r1,r2,r3, addr) \
    asm volatile("ldmatrix.sync.aligned.m8n8.x4.shared.b16 {%0,%1,%2,%3}, [%4];" \
        : "=r"(r0), "=r"(r1), "=r"(r2), "=r"(r3) : "r"(addr))
#define LDMATRIX_X4_T(r0,r1,r2,r3, addr) \
    asm volatile("ldmatrix.sync.aligned.m8n8.x4.trans.shared.b16 {%0,%1,%2,%3}, [%4];" \
        : "=r"(r0), "=r"(r1), "=r"(r2), "=r"(r3) : "r"(addr))

#define MMA_F16(c, a, b0, b1) \
    asm volatile("mma.sync.aligned.m16n8k16.row.col.f32.f16.f16.f32 " \
        "{%0,%1,%2,%3}, {%4,%5,%6,%7}, {%8,%9}, {%0,%1,%2,%3};" \
        : "+f"((c)[0]), "+f"((c)[1]), "+f"((c)[2]), "+f"((c)[3]) \
        : "r"((a)[0]), "r"((a)[1]), "r"((a)[2]), "r"((a)[3]), "r"(b0), "r"(b1))

// ---------------- routing (fused with gather, R14 version) ----------------
__global__ void init_kernel() { if (threadIdx.x < NE) g_counts[threadIdx.x] = 0; }

__global__ void route_gather_kernel(const float* __restrict__ x,
                                    const float* __restrict__ gw,
                                    const float* __restrict__ gb, int T) {
    int warp = (blockIdx.x * blockDim.x + threadIdx.x) >> 5;
    int lane = threadIdx.x & 31;
    if (warp >= T) return;
    const float* xr = x + (size_t)warp * DM;
    float acc[NE];
    #pragma unroll
    for (int e = 0; e < NE; e++) acc[e] = 0.f;
    for (int d = lane; d < DM; d += 32) {
        float xv = xr[d];
        const float4* g4 = (const float4*)(gw + (size_t)d * NE);
        float4 a = g4[0], b = g4[1];
        acc[0] += xv*a.x; acc[1] += xv*a.y; acc[2] += xv*a.z; acc[3] += xv*a.w;
        acc[4] += xv*b.x; acc[5] += xv*b.y; acc[6] += xv*b.z; acc[7] += xv*b.w;
    }
    #pragma unroll
    for (int e = 0; e < NE; e++)
        #pragma unroll
        for (int o = 16; o > 0; o >>= 1) acc[e] += __shfl_xor_sync(0xFFFFFFFFu, acc[e], o);

    int i1 = 0, i2 = 0, s1 = 0, s2 = 0;
    if (lane == 0) {
        float v[NE];
        #pragma unroll
        for (int e = 0; e < NE; e++) v[e] = acc[e] + gb[e];
        i1 = 0;
        #pragma unroll
        for (int e = 1; e < NE; e++) if (v[e] > v[i1]) i1 = e;
        i2 = (i1 == 0) ? 1 : 0;
        #pragma unroll
        for (int e = 0; e < NE; e++) if (e != i1 && v[e] > v[i2]) i2 = e;
        float e2 = expf(v[i2] - v[i1]);
        float s = 1.f + e2;
        s1 = atomicAdd(&g_counts[i1], 1);
        g_tok[i1][s1] = warp; g_gate[i1][s1] = 1.f / s;
        s2 = atomicAdd(&g_counts[i2], 1);
        g_tok[i2][s2] = warp; g_gate[i2][s2] = e2 / s;
    }
    i1 = __shfl_sync(0xFFFFFFFFu, i1, 0);
    i2 = __shfl_sync(0xFFFFFFFFu, i2, 0);
    s1 = __shfl_sync(0xFFFFFFFFu, s1, 0);
    s2 = __shfl_sync(0xFFFFFFFFu, s2, 0);

    const float4* src = (const float4*)xr;
    uint2* d1 = (uint2*)(g_Xgh + ((size_t)i1 * TMAX + s1) * DM);
    uint2* d2 = (uint2*)(g_Xgh + ((size_t)i2 * TMAX + s2) * DM);
    #pragma unroll
    for (int j = 0; j < 8; j++) {
        int idx = lane + j * 32;
        float4 v = src[idx];
        __half2 h0 = __floats2half2_rn(v.x, v.y);
        __half2 h1 = __floats2half2_rn(v.z, v.w);
        uint2 o;
        o.x = *reinterpret_cast<uint32_t*>(&h0);
        o.y = *reinterpret_cast<uint32_t*>(&h1);
        d1[idx] = o;
        d2[idx] = o;
    }
}

// fp32 -> fp16 weight conversion
__global__ void conv_half_kernel(const float4* __restrict__ src, uint4* __restrict__ dst, int n8) {
    int i = blockIdx.x * blockDim.x + threadIdx.x;
    if (i >= n8) return;
    float4 v0 = src[i * 2], v1 = src[i * 2 + 1];
    __half2 h0 = __floats2half2_rn(v0.x, v0.y);
    __half2 h1 = __floats2half2_rn(v0.z, v0.w);
    __half2 h2 = __floats2half2_rn(v1.x, v1.y);
    __half2 h3 = __floats2half2_rn(v1.z, v1.w);
    uint4 o;
    o.x = *reinterpret_cast<uint32_t*>(&h0);
    o.y = *reinterpret_cast<uint32_t*>(&h1);
    o.z = *reinterpret_cast<uint32_t*>(&h2);
    o.w = *reinterpret_cast<uint32_t*>(&h3);
    dst[i] = o;
}

// ---------------- fp16 mma grouped GEMM ----------------
// CTA 64x128, 256 threads = 8 warps (2x4), warp tile 32x32, k-chunk 32.
// smem (halves): A [64][40], B [32][136], 4-stage pipeline. 3 CTAs/SM.
#define ASTRH 40
#define BSTRH 136
#define ABUFB (64 * ASTRH * 2)           // 5120 B
#define BBUFB (32 * BSTRH * 2)           // 8704 B
#define BUFB  (ABUFB + BBUFB)            // 13824 B
#define NSTAGE 4
#define SMEM_DYN (NSTAGE * BUFB)         // 55296 B

template<int KDIM, int NDIM, bool GELU_OUT>
__global__ void __launch_bounds__(256, 3)
gemm_mma(const __half* __restrict__ Bmat, const float* __restrict__ bias,
         float* __restrict__ outp) {
    const int e = blockIdx.z;
    const int count = g_counts[e];
    const int m0 = blockIdx.x * 64;
    if (m0 >= count) return;
    const size_t base = (size_t)e * TMAX;
    const int n0 = blockIdx.y * 128;

    extern __shared__ char smraw[];
    const uint32_t su = smem_u32(smraw);

    const int tid  = threadIdx.x;
    const int wid  = tid >> 5;
    const int lane = tid & 31;
    const int g    = lane >> 2;
    const int tg   = lane & 3;
    const int wr   = wid & 1;    // 2 warp rows x 32
    const int wc   = wid >> 1;   // 4 warp cols x 32

    const __half* Asrc = (GELU_OUT ? g_Xgh : g_Hh) + (base + m0) * KDIM;
    const __half* Bsrc = Bmat + (size_t)e * KDIM * NDIM + n0;

    // loader mapping: A 64 rows x 4 chunks = 256 cp (1/thread)
    const int am = tid >> 2;
    const int ac = tid & 3;
    // B 32 rows x 16 chunks = 512 cp (2/thread)
    const int bk = tid >> 3;
    const int bc = (tid & 7) * 2;

    const int lane_r  = (lane & 7) + ((lane >> 3) & 1) * 8;
    const int lane_k8 = (lane >> 4) * 16;

    float c[2][4][4];
    #pragma unroll
    for (int i = 0; i < 2; i++)
        #pragma unroll
        for (int j = 0; j < 4; j++)
            #pragma unroll
            for (int k = 0; k < 4; k++) c[i][j][k] = 0.f;

    const int KC = KDIM / 32;

    #define LOAD_TILES(kc_, buf_) do { \
        uint32_t sa = su + (buf_) * BUFB; \
        uint32_t sb = sa + ABUFB; \
        const __half* asp = Asrc + (size_t)am * KDIM + (kc_) * 32; \
        CP_ASYNC16(sa + (uint32_t)(am * 80 + ac * 16), asp + ac * 8); \
        const __half* bsp = Bsrc + (size_t)((kc_) * 32 + bk) * NDIM; \
        _Pragma("unroll") \
        for (int j = 0; j < 2; j++) \
            CP_ASYNC16(sb + (uint32_t)(bk * 272 + (bc + j) * 16), bsp + (bc + j) * 8); \
    } while (0)

    LOAD_TILES(0, 0); CP_COMMIT();
    LOAD_TILES(1, 1); CP_COMMIT();
    LOAD_TILES(2, 2); CP_COMMIT();

    for (int kc = 0; kc < KC; kc++) {
        CP_WAIT2();
        __syncthreads();
        if (kc + 3 < KC) LOAD_TILES(kc + 3, (kc + 3) & 3);
        CP_COMMIT();

        const uint32_t sa = su + (kc & 3) * BUFB;
        const uint32_t sb = sa + ABUFB;
        const uint32_t a_base = sa + (uint32_t)((wr * 32 + lane_r) * 80) + lane_k8;
        const uint32_t b_base = sb + (uint32_t)(lane_r * 272 + wc * 64) + lane_k8;

        #pragma unroll
        for (int ks = 0; ks < 2; ks++) {
            uint32_t a[2][4];
            #pragma unroll
            for (int mf = 0; mf < 2; mf++)
                LDMATRIX_X4(a[mf][0], a[mf][1], a[mf][2], a[mf][3],
                            a_base + mf * 1280 + ks * 32);
            uint32_t b[4][2];
            #pragma unroll
            for (int np = 0; np < 2; np++) {
                uint32_t r0, r1, r2, r3;
                LDMATRIX_X4_T(r0, r1, r2, r3, b_base + ks * 4352 + np * 32);
                b[np * 2 + 0][0] = r0; b[np * 2 + 0][1] = r1;
                b[np * 2 + 1][0] = r2; b[np * 2 + 1][1] = r3;
            }
            #pragma unroll
            for (int mf = 0; mf < 2; mf++)
                #pragma unroll
                for (int nf = 0; nf < 4; nf++)
                    MMA_F16(c[mf][nf], a[mf], b[nf][0], b[nf][1]);
        }
    }

    // -------- epilogue --------
    #pragma unroll
    for (int mf = 0; mf < 2; mf++) {
        #pragma unroll
        for (int half_ = 0; half_ < 2; half_++) {
            int rl = wr * 32 + mf * 16 + g + half_ * 8;
            int m = m0 + rl;
            if (m >= count) continue;
            if (GELU_OUT) {
                __half* hrow = g_Hh + (base + m) * FFN_;
                #pragma unroll
                for (int nf = 0; nf < 4; nf++) {
                    int col = n0 + wc * 32 + nf * 8 + 2 * tg;
                    float2 bb = *(const float2*)(bias + (size_t)e * NDIM + col);
                    __half2 hv = __floats2half2_rn(
                        gelu_exact(c[mf][nf][half_ * 2 + 0] + bb.x),
                        gelu_exact(c[mf][nf][half_ * 2 + 1] + bb.y));
                    *reinterpret_cast<__half2*>(hrow + col) = hv;
                }
            } else {
                int tok = g_tok[e][m];
                float gt = g_gate[e][m];
                float* orow = outp + (size_t)tok * DM;
                #pragma unroll
                for (int nf = 0; nf < 4; nf++) {
                    int col = n0 + wc * 32 + nf * 8 + 2 * tg;
                    float2 bb = *(const float2*)(bias + (size_t)e * NDIM + col);
                    atomicAdd(orow + col + 0, gt * (c[mf][nf][half_ * 2 + 0] + bb.x));
                    atomicAdd(orow + col + 1, gt * (c[mf][nf][half_ * 2 + 1] + bb.y));
                }
            }
        }
    }
}

// ---------------- launch ----------------
extern "C" void kernel_launch(void* const* d_in, const int* in_sizes, int n_in,
                              void* d_out, int out_size) {
    const float* x  = (const float*)d_in[0];
    const float* gw = (const float*)d_in[1];
    const float* gb = (const float*)d_in[2];
    const float* w1 = (const float*)d_in[3];
    const float* b1 = (const float*)d_in[4];
    const float* w2 = (const float*)d_in[5];
    const float* b2 = (const float*)d_in[6];
    float* out = (float*)d_out;
    const int T = in_sizes[0] / DM;

    __half* w1h; cudaGetSymbolAddress((void**)&w1h, g_w1h);
    __half* w2h; cudaGetSymbolAddress((void**)&w2h, g_w2h);

    static cudaStream_t s1 = nullptr;
    static cudaEvent_t evRoot = nullptr, evW1 = nullptr, evW2 = nullptr;
    static int once = 0;
    if (!once) {
        cudaStreamCreateWithFlags(&s1, cudaStreamNonBlocking);
        cudaEventCreateWithFlags(&evRoot, cudaEventDisableTiming);
        cudaEventCreateWithFlags(&evW1, cudaEventDisableTiming);
        cudaEventCreateWithFlags(&evW2, cudaEventDisableTiming);
        cudaFuncSetAttribute(gemm_mma<DM, FFN_, true>,
                             cudaFuncAttributeMaxDynamicSharedMemorySize, SMEM_DYN);
        cudaFuncSetAttribute(gemm_mma<FFN_, DM, false>,
                             cudaFuncAttributeMaxDynamicSharedMemorySize, SMEM_DYN);
        once = 1;
    }

    const int n8 = NE * DM * FFN_ / 8;

    // fork side stream: conv w1, memset(out), conv w2
    cudaEventRecord(evRoot, 0);
    cudaStreamWaitEvent(s1, evRoot, 0);
    conv_half_kernel<<<(n8 + 255) / 256, 256, 0, s1>>>((const float4*)w1, (uint4*)w1h, n8);
    cudaEventRecord(evW1, s1);
    cudaMemsetAsync(d_out, 0, (size_t)out_size * sizeof(float), s1);
    conv_half_kernel<<<(n8 + 255) / 256, 256, 0, s1>>>((const float4*)w2, (uint4*)w2h, n8);
    cudaEventRecord(evW2, s1);

    // main stream: routing (fused gather)
    init_kernel<<<1, 32>>>();
    route_gather_kernel<<<(T + 7) / 8, 256>>>(x, gw, gb, T);

    // join w1, run GEMM1 (conv w2 + memset overlap on s1)
    cudaStreamWaitEvent(0, evW1, 0);
    gemm_mma<DM, FFN_, true><<<dim3(T / 64, FFN_ / 128, NE), 256, SMEM_DYN>>>(w1h, b1, nullptr);

    // join w2 (+memset), run GEMM2
    cudaStreamWaitEvent(0, evW2, 0);
    gemm_mma<FFN_, DM, false><<<dim3(T / 64, DM / 128, NE), 256, SMEM_DYN>>>(w2h, b2, out);
}